// round 5
// baseline (speedup 1.0000x reference)
#include <cuda_runtime.h>
#include <cstdint>
#include <cstddef>

// ============================================================================
// RNNLayers: 2-layer LSTM (Keras semantics, activation=selu), B=64, T=2048,
// F=64, H=128.  Plan:
//   1) GEMM1: xz = x  @ W1 + b1   -> g_xz   [131072 x 512]
//   2) scan1: LSTM recurrence     -> g_h1   [131072 x 128]
//   3) GEMM2: xz = h1 @ W2 + b2   -> g_xz
//   4) scan2: LSTM recurrence     -> d_out  [131072 x 128]
// ============================================================================

typedef unsigned long long ull;

#define BATCH 64
#define TSEQ  2048
#define FIN   64
#define HID   128

#define SELU_LAM 1.0507009873554804934193349852946f
#define SELU_ALF 1.6732632423543772848170429916717f

__device__ float g_xz[(size_t)BATCH * TSEQ * 4 * HID];  // 256 MB scratch
__device__ float g_h1[(size_t)BATCH * TSEQ * HID];      //  64 MB scratch

__device__ __forceinline__ void fma2(ull& d, ull a, ull b) {
    asm("fma.rn.f32x2 %0, %1, %2, %0;" : "+l"(d) : "l"(a), "l"(b));
}
__device__ __forceinline__ ull pack2(float lo, float hi) {
    ull r; asm("mov.b64 %0, {%1, %2};" : "=l"(r) : "f"(lo), "f"(hi)); return r;
}
__device__ __forceinline__ float2 unpack2(ull v) {
    float2 r; asm("mov.b64 {%0, %1}, %2;" : "=f"(r.x), "=f"(r.y) : "l"(v)); return r;
}
__device__ __forceinline__ ull d2u(double d) { return (ull)__double_as_longlong(d); }

// ============================================================================
// GEMM: Y[M,512] = X[M,K] @ W[K,512] + bias.  BM=128, BN=128, K loaded whole.
// 256 threads; thread (tmi = tid&15, tn = (tid>>4)*8) owns rows {tmi+16r} x
// cols [tn, tn+8).  f32x2 accumulators paired along N.
// ============================================================================
template<int K>
__global__ __launch_bounds__(256, 1)
void gemm_xz(const float* __restrict__ X, const float* __restrict__ W,
             const float* __restrict__ bias, float* __restrict__ Y) {
    extern __shared__ float sm[];
    float* s_a = sm;                     // [128][K+1]  (pad -> conflict-free a-loads)
    float* s_b = sm + 128 * (K + 1);     // [K][128]
    const int tid = threadIdx.x;
    const int bm  = blockIdx.x * 128;
    const int bn  = blockIdx.y * 128;

    // Load A tile (row-major, +1 pad). Consecutive tid -> consecutive k: coalesced.
    #pragma unroll 8
    for (int i = tid; i < 128 * K; i += 256) {
        int m = i / K, k = i - m * K;
        s_a[m * (K + 1) + k] = X[(size_t)(bm + m) * K + k];
    }
    // Load B tile (vectorized, coalesced).
    #pragma unroll 4
    for (int i = tid * 4; i < K * 128; i += 1024) {
        int k = i >> 7, n = i & 127;
        *(float4*)(s_b + k * 128 + n) = *(const float4*)(W + (size_t)k * 512 + bn + n);
    }
    __syncthreads();

    const int tmi = tid & 15;
    const int tn  = (tid >> 4) << 3;
    ull acc[8][4] = {};
    const float* sbp = s_b + tn;

    #pragma unroll 4
    for (int k = 0; k < K; ++k) {
        float4 b0 = *(const float4*)(sbp + k * 128);
        float4 b1 = *(const float4*)(sbp + k * 128 + 4);
        ull bb0 = pack2(b0.x, b0.y), bb1 = pack2(b0.z, b0.w);
        ull bb2 = pack2(b1.x, b1.y), bb3 = pack2(b1.z, b1.w);
        #pragma unroll
        for (int r = 0; r < 8; ++r) {
            float a = s_a[(tmi + (r << 4)) * (K + 1) + k];
            ull aa = pack2(a, a);
            fma2(acc[r][0], aa, bb0);
            fma2(acc[r][1], aa, bb1);
            fma2(acc[r][2], aa, bb2);
            fma2(acc[r][3], aa, bb3);
        }
    }

    float4 bv0 = *(const float4*)(bias + bn + tn);
    float4 bv1 = *(const float4*)(bias + bn + tn + 4);
    #pragma unroll
    for (int r = 0; r < 8; ++r) {
        int row = bm + tmi + (r << 4);
        float2 c0 = unpack2(acc[r][0]);
        float2 c1 = unpack2(acc[r][1]);
        float2 c2 = unpack2(acc[r][2]);
        float2 c3 = unpack2(acc[r][3]);
        float4 o0 = make_float4(c0.x + bv0.x, c0.y + bv0.y, c1.x + bv0.z, c1.y + bv0.w);
        float4 o1 = make_float4(c2.x + bv1.x, c2.y + bv1.y, c3.x + bv1.z, c3.y + bv1.w);
        float* yp = Y + (size_t)row * 512 + bn + tn;
        *(float4*)yp       = o0;
        *(float4*)(yp + 4) = o1;
    }
}

// ============================================================================
// LSTM scan.  One CTA per batch row; 512 threads, one gate column each.
// U column (128 fp32): first KREG values in registers (as f32x2 pairs),
// remaining KSM values in smem as [chunk][512 cols][4] (LDS.128 conflict-free).
// Per step: z[col] = xz[t,col] + dot(h, U[:,col]) via fma.rn.f32x2; then
// threads 0..127 apply gates (c kept in their registers) and publish h.
// ============================================================================
#define KREG 96
#define KSM  32

__global__ __launch_bounds__(512, 1)
void lstm_scan(const float* __restrict__ xz, const float* __restrict__ U,
               float* __restrict__ hout, int T) {
    extern __shared__ float sm[];
    float* s_u = sm;                // [KSM/4][512][4] = 16384 floats (64 KB)
    float* s_h = sm + 16384;        // 128 floats, 16B aligned
    float* s_z = sm + 16384 + 128;  // 512 floats

    const int col = threadIdx.x;
    const int b   = blockIdx.x;

    // --- one-time U load -----------------------------------------------------
    ull ureg[KREG / 2];
    #pragma unroll
    for (int q = 0; q < KREG / 2; ++q) {
        float u0 = U[(size_t)(2 * q)     * 512 + col];
        float u1 = U[(size_t)(2 * q + 1) * 512 + col];
        ureg[q] = pack2(u0, u1);
    }
    #pragma unroll
    for (int kk = 0; kk < KSM; ++kk) {
        s_u[(kk >> 2) * 2048 + (col << 2) + (kk & 3)] = U[(size_t)(KREG + kk) * 512 + col];
    }
    if (col < HID) s_h[col] = 0.0f;
    float c = 0.0f;
    __syncthreads();

    const float* xzp = xz + (size_t)b * T * 512 + col;
    float* hp = hout + (size_t)b * T * HID;
    float xz_pref = xzp[0];

    for (int t = 0; t < T; ++t) {
        float xz_cur = xz_pref;
        int tnx = (t + 1 < T) ? t + 1 : t;
        xz_pref = __ldcs(xzp + (size_t)tnx * 512);   // prefetch next step's xz

        // dot(h, U[:,col]) — register-resident part
        ull acc0 = 0ull, acc1 = 0ull;
        #pragma unroll
        for (int q = 0; q < KREG / 4; ++q) {
            double2 hd = *(const double2*)(s_h + (q << 2));
            fma2(acc0, d2u(hd.x), ureg[2 * q]);
            fma2(acc1, d2u(hd.y), ureg[2 * q + 1]);
        }
        // smem-resident part
        #pragma unroll
        for (int q = 0; q < KSM / 4; ++q) {
            double2 hd = *(const double2*)(s_h + KREG + (q << 2));
            double2 ud = *(const double2*)(s_u + q * 2048 + (col << 2));
            fma2(acc0, d2u(hd.x), d2u(ud.x));
            fma2(acc1, d2u(hd.y), d2u(ud.y));
        }
        float2 a0 = unpack2(acc0), a1 = unpack2(acc1);
        float z = xz_cur + ((a0.x + a0.y) + (a1.x + a1.y));
        s_z[col] = z;
        __syncthreads();

        if (col < HID) {
            float zi = s_z[col];
            float zf = s_z[col + HID];
            float zg = s_z[col + 2 * HID];
            float zo = s_z[col + 3 * HID];
            float ig = 1.0f / (1.0f + expf(-zi));
            float fg = 1.0f / (1.0f + expf(-zf));
            float gg = (zg > 0.0f) ? SELU_LAM * zg : (SELU_LAM * SELU_ALF) * expm1f(zg);
            float og = 1.0f / (1.0f + expf(-zo));
            c = fg * c + ig * gg;
            float sc = (c > 0.0f) ? SELU_LAM * c : (SELU_LAM * SELU_ALF) * expm1f(c);
            float h = og * sc;
            s_h[col] = h;
            hp[(size_t)t * HID + col] = h;
        }
        __syncthreads();
    }
}

// ============================================================================
// kernel_launch
// Inputs (metadata order): x, W1, U1, b1, W2, U2, b2 — all fp32.
// Output: h2 sequence [B, T, H] fp32.
// ============================================================================
extern "C" void kernel_launch(void* const* d_in, const int* in_sizes, int n_in,
                              void* d_out, int out_size) {
    (void)in_sizes; (void)n_in; (void)out_size;
    const float* x  = (const float*)d_in[0];
    const float* W1 = (const float*)d_in[1];
    const float* U1 = (const float*)d_in[2];
    const float* b1 = (const float*)d_in[3];
    const float* W2 = (const float*)d_in[4];
    const float* U2 = (const float*)d_in[5];
    const float* b2 = (const float*)d_in[6];
    float* out = (float*)d_out;

    void *pxz = nullptr, *ph1 = nullptr;
    cudaGetSymbolAddress(&pxz, g_xz);
    cudaGetSymbolAddress(&ph1, g_h1);
    float* xz = (float*)pxz;
    float* h1 = (float*)ph1;

    const int smemA = (128 * (FIN + 1) + FIN * 128) * 4;    //  66048 B
    const int smemB = (128 * (HID + 1) + HID * 128) * 4;    // 131584 B
    const int smemS = (16384 + 128 + 512) * 4;              //  68096 B
    cudaFuncSetAttribute(gemm_xz<FIN>, cudaFuncAttributeMaxDynamicSharedMemorySize, smemA);
    cudaFuncSetAttribute(gemm_xz<HID>, cudaFuncAttributeMaxDynamicSharedMemorySize, smemB);
    cudaFuncSetAttribute(lstm_scan,    cudaFuncAttributeMaxDynamicSharedMemorySize, smemS);

    dim3 gg((BATCH * TSEQ) / 128, 4);

    gemm_xz<FIN><<<gg, 256, smemA>>>(x, W1, b1, xz);
    lstm_scan<<<BATCH, 512, smemS>>>(xz, U1, h1, TSEQ);
    gemm_xz<HID><<<gg, 256, smemB>>>(h1, W2, b2, xz);
    lstm_scan<<<BATCH, 512, smemS>>>(xz, U2, out, TSEQ);
}

// round 6
// speedup vs baseline: 1.6498x; 1.6498x over previous
#include <cuda_runtime.h>
#include <cstdint>
#include <cstddef>

// ============================================================================
// RNNLayers: 2-layer LSTM (Keras semantics, activation=selu), B=64, T=2048,
// F=64, H=128.
//   1) GEMM1: xz = x  @ W1 + b1   -> g_xz   [131072 x 512]
//   2) scan1: LSTM recurrence     -> g_h1   [131072 x 128]
//   3) GEMM2: xz = h1 @ W2 + b2   -> g_xz
//   4) scan2: LSTM recurrence     -> d_out  [131072 x 128]
// ============================================================================

typedef unsigned long long ull;

#define BATCH 64
#define TSEQ  2048
#define FIN   64
#define HID   128

#define SELU_LAM 1.0507009873554804934193349852946f
#define SELU_ALF 1.6732632423543772848170429916717f

__device__ float g_xz[(size_t)BATCH * TSEQ * 4 * HID];  // 256 MB scratch
__device__ float g_h1[(size_t)BATCH * TSEQ * HID];      //  64 MB scratch

__device__ __forceinline__ void fma2(ull& d, ull a, ull b) {
    asm("fma.rn.f32x2 %0, %1, %2, %0;" : "+l"(d) : "l"(a), "l"(b));
}
__device__ __forceinline__ ull pack2(float lo, float hi) {
    ull r; asm("mov.b64 %0, {%1, %2};" : "=l"(r) : "f"(lo), "f"(hi)); return r;
}
__device__ __forceinline__ float2 unpack2(ull v) {
    float2 r; asm("mov.b64 {%0, %1}, %2;" : "=f"(r.x), "=f"(r.y) : "l"(v)); return r;
}
__device__ __forceinline__ ull d2u(double d) { return (ull)__double_as_longlong(d); }

// ============================================================================
// GEMM: Y[M,512] = X[M,K] @ W[K,512] + bias.  BM=128, BN=128, K loaded whole.
// 256 threads; thread (tmi = tid&15, tn = (tid>>4)*8) owns rows {tmi+16r} x
// cols [tn, tn+8).  f32x2 accumulators paired along N.
// ============================================================================
template<int K>
__global__ __launch_bounds__(256, 1)
void gemm_xz(const float* __restrict__ X, const float* __restrict__ W,
             const float* __restrict__ bias, float* __restrict__ Y) {
    extern __shared__ float sm[];
    float* s_a = sm;                     // [128][K+1]
    float* s_b = sm + 128 * (K + 1);     // [K][128]
    const int tid = threadIdx.x;
    const int bm  = blockIdx.x * 128;
    const int bn  = blockIdx.y * 128;

    #pragma unroll 8
    for (int i = tid; i < 128 * K; i += 256) {
        int m = i / K, k = i - m * K;
        s_a[m * (K + 1) + k] = X[(size_t)(bm + m) * K + k];
    }
    #pragma unroll 4
    for (int i = tid * 4; i < K * 128; i += 1024) {
        int k = i >> 7, n = i & 127;
        *(float4*)(s_b + k * 128 + n) = *(const float4*)(W + (size_t)k * 512 + bn + n);
    }
    __syncthreads();

    const int tmi = tid & 15;
    const int tn  = (tid >> 4) << 3;
    ull acc[8][4] = {};
    const float* sbp = s_b + tn;

    #pragma unroll 4
    for (int k = 0; k < K; ++k) {
        float4 b0 = *(const float4*)(sbp + k * 128);
        float4 b1 = *(const float4*)(sbp + k * 128 + 4);
        ull bb0 = pack2(b0.x, b0.y), bb1 = pack2(b0.z, b0.w);
        ull bb2 = pack2(b1.x, b1.y), bb3 = pack2(b1.z, b1.w);
        #pragma unroll
        for (int r = 0; r < 8; ++r) {
            float a = s_a[(tmi + (r << 4)) * (K + 1) + k];
            ull aa = pack2(a, a);
            fma2(acc[r][0], aa, bb0);
            fma2(acc[r][1], aa, bb1);
            fma2(acc[r][2], aa, bb2);
            fma2(acc[r][3], aa, bb3);
        }
    }

    float4 bv0 = *(const float4*)(bias + bn + tn);
    float4 bv1 = *(const float4*)(bias + bn + tn + 4);
    #pragma unroll
    for (int r = 0; r < 8; ++r) {
        int row = bm + tmi + (r << 4);
        float2 c0 = unpack2(acc[r][0]);
        float2 c1 = unpack2(acc[r][1]);
        float2 c2 = unpack2(acc[r][2]);
        float2 c3 = unpack2(acc[r][3]);
        float4 o0 = make_float4(c0.x + bv0.x, c0.y + bv0.y, c1.x + bv0.z, c1.y + bv0.w);
        float4 o1 = make_float4(c2.x + bv1.x, c2.y + bv1.y, c3.x + bv1.z, c3.y + bv1.w);
        float* yp = Y + (size_t)row * 512 + bn + tn;
        *(float4*)yp       = o0;
        *(float4*)(yp + 4) = o1;
    }
}

// ============================================================================
// LSTM scan.  One CTA per batch row; 512 threads.
// Thread layout: gate = tid&3 (i,f,g,o), j = tid>>2 (h column 0..127).
// A 4-lane group owns all 4 gates of one h column -> gate gather via 3 warp
// shuffles, c-update distributed over all 16 warps, ONE barrier per step.
// U column resident: KREG values in registers (f32x2 pairs), KSM in smem laid
// out [chunk][tid][4] so each LDS.128 is conflict-free.  h double-buffered.
// All transcendentals via MUFU intrinsics (__expf, __fdividef).
// ============================================================================
#define KREG 80
#define KSM  48

__global__ __launch_bounds__(512, 1)
void lstm_scan(const float* __restrict__ xz, const float* __restrict__ U,
               float* __restrict__ hout, int T) {
    extern __shared__ float sm[];
    float* s_u = sm;                       // [KSM/4][512][4] = 24576 floats
    float* s_h = sm + (KSM / 4) * 2048;    // [2][128]

    const int tid  = threadIdx.x;
    const int gate = tid & 3;
    const int j    = tid >> 2;
    const int ucol = (gate << 7) + j;      // column in U / xz
    const int b    = blockIdx.x;

    // --- one-time U load -----------------------------------------------------
    ull ureg[KREG / 2];
    #pragma unroll
    for (int q = 0; q < KREG / 2; ++q) {
        float u0 = U[(size_t)(2 * q)     * 512 + ucol];
        float u1 = U[(size_t)(2 * q + 1) * 512 + ucol];
        ureg[q] = pack2(u0, u1);
    }
    #pragma unroll
    for (int kk = 0; kk < KSM; ++kk) {
        s_u[(kk >> 2) * 2048 + (tid << 2) + (kk & 3)] = U[(size_t)(KREG + kk) * 512 + ucol];
    }
    if (tid < HID) s_h[tid] = 0.0f;        // h buffer 0
    float c = 0.0f;
    __syncthreads();

    const float* xzp = xz + (size_t)b * T * 512 + ucol;
    float* hp = hout + (size_t)b * T * HID + j;
    float xz_pref = __ldcs(xzp);
    const int lane_base = (tid & 31) & ~3;

    for (int t = 0; t < T; ++t) {
        float xz_cur = xz_pref;
        int tnx = (t + 1 < T) ? t + 1 : t;
        xz_pref = __ldcs(xzp + (size_t)tnx * 512);   // prefetch next step's xz

        const float* hcur = s_h + ((t & 1) << 7);

        // z = xz + dot(h, U[:,ucol])   (f32x2 MACs, 4 accumulator chains)
        ull acc[4] = {0ull, 0ull, 0ull, 0ull};
        #pragma unroll
        for (int q = 0; q < KREG / 4; ++q) {
            double2 hd = *(const double2*)(hcur + (q << 2));
            fma2(acc[(2 * q) & 3],     d2u(hd.x), ureg[2 * q]);
            fma2(acc[(2 * q + 1) & 3], d2u(hd.y), ureg[2 * q + 1]);
        }
        #pragma unroll
        for (int q = 0; q < KSM / 4; ++q) {
            double2 hd = *(const double2*)(hcur + KREG + (q << 2));
            double2 ud = *(const double2*)(s_u + q * 2048 + (tid << 2));
            fma2(acc[(2 * q) & 3],     d2u(hd.x), d2u(ud.x));
            fma2(acc[(2 * q + 1) & 3], d2u(hd.y), d2u(ud.y));
        }
        float2 a0 = unpack2(acc[0]), a1 = unpack2(acc[1]);
        float2 a2 = unpack2(acc[2]), a3 = unpack2(acc[3]);
        float z = xz_cur + (((a0.x + a0.y) + (a1.x + a1.y)) +
                            ((a2.x + a2.y) + (a3.x + a3.y)));

        // activation (branchless: sigmoid for gates i/f/o, selu for g)
        float e   = __expf(gate == 2 ? z : -z);
        float sig = __fdividef(1.0f, 1.0f + e);
        float sel = (z > 0.0f) ? SELU_LAM * z : (SELU_LAM * SELU_ALF) * (e - 1.0f);
        float act = (gate == 2) ? sel : sig;

        // gather all four gates into lane gate==0 via warp shuffles
        float af = __shfl_sync(0xffffffffu, act, lane_base + 1);
        float ag = __shfl_sync(0xffffffffu, act, lane_base + 2);
        float ao = __shfl_sync(0xffffffffu, act, lane_base + 3);

        if (gate == 0) {
            c = af * c + act * ag;
            float sc = (c > 0.0f) ? SELU_LAM * c
                                  : (SELU_LAM * SELU_ALF) * (__expf(c) - 1.0f);
            float h = ao * sc;
            s_h[(((t + 1) & 1) << 7) + j] = h;
            hp[(size_t)t * HID] = h;
        }
        __syncthreads();
    }
}

// ============================================================================
// kernel_launch
// Inputs (metadata order): x, W1, U1, b1, W2, U2, b2 — all fp32.
// Output: h2 sequence [B, T, H] fp32.
// ============================================================================
extern "C" void kernel_launch(void* const* d_in, const int* in_sizes, int n_in,
                              void* d_out, int out_size) {
    (void)in_sizes; (void)n_in; (void)out_size;
    const float* x  = (const float*)d_in[0];
    const float* W1 = (const float*)d_in[1];
    const float* U1 = (const float*)d_in[2];
    const float* b1 = (const float*)d_in[3];
    const float* W2 = (const float*)d_in[4];
    const float* U2 = (const float*)d_in[5];
    const float* b2 = (const float*)d_in[6];
    float* out = (float*)d_out;

    void *pxz = nullptr, *ph1 = nullptr;
    cudaGetSymbolAddress(&pxz, g_xz);
    cudaGetSymbolAddress(&ph1, g_h1);
    float* xz = (float*)pxz;
    float* h1 = (float*)ph1;

    const int smemA = (128 * (FIN + 1) + FIN * 128) * 4;    //  66048 B
    const int smemB = (128 * (HID + 1) + HID * 128) * 4;    // 131584 B
    const int smemS = ((KSM / 4) * 2048 + 256) * 4;         //  99328 B
    cudaFuncSetAttribute(gemm_xz<FIN>, cudaFuncAttributeMaxDynamicSharedMemorySize, smemA);
    cudaFuncSetAttribute(gemm_xz<HID>, cudaFuncAttributeMaxDynamicSharedMemorySize, smemB);
    cudaFuncSetAttribute(lstm_scan,    cudaFuncAttributeMaxDynamicSharedMemorySize, smemS);

    dim3 gg((BATCH * TSEQ) / 128, 4);

    gemm_xz<FIN><<<gg, 256, smemA>>>(x, W1, b1, xz);
    lstm_scan<<<BATCH, 512, smemS>>>(xz, U1, h1, TSEQ);
    gemm_xz<HID><<<gg, 256, smemB>>>(h1, W2, b2, xz);
    lstm_scan<<<BATCH, 512, smemS>>>(xz, U2, out, TSEQ);
}